// round 8
// baseline (speedup 1.0000x reference)
#include <cuda_runtime.h>
#include <math.h>

#define D 64
#define S 16
#define NB 16   // batches per CTA in k_main (processed in pairs)

// ---------------- device scratch (static, no runtime alloc) ----------------
// C stored PACKED along d: float pair {C[2*d2][e], C[2*d2+1][e]} at offset d2*128 + 2*e
__device__ float g_Cr[64 * 64];
__device__ float g_Ci[64 * 64];
__device__ int   g_count;

// ---------------- f32x2 packed helpers ----------------
__device__ __forceinline__ void ffma2(unsigned long long& d_,
                                      unsigned long long a_, unsigned long long b_) {
    asm("fma.rn.f32x2 %0, %1, %2, %0;" : "+l"(d_) : "l"(a_), "l"(b_));
}
__device__ __forceinline__ float hadd2(unsigned long long v) {
    float lo, hi;
    asm("mov.b64 {%0, %1}, %2;" : "=f"(lo), "=f"(hi) : "l"(v));
    return lo + hi;
}
__device__ __forceinline__ unsigned long long L64(const float* p) {
    return *reinterpret_cast<const unsigned long long*>(p);
}

// ---------------- kernel 0: C = Wq^T * conj(Wk) (packed layout), zero counter ----------------
__global__ void k_prep(const float* __restrict__ wqr, const float* __restrict__ wqi,
                       const float* __restrict__ wkr, const float* __restrict__ wki) {
    int d = blockIdx.x;   // 64 blocks
    int e = threadIdx.x;  // 64 threads
    if (d == 0 && e == 0) g_count = 0;
    float cr = 0.f, ci = 0.f;
#pragma unroll 8
    for (int j = 0; j < 64; ++j) {
        float aqr = wqr[j * 64 + d], aqi = wqi[j * 64 + d];
        float bkr = wkr[j * 64 + e], bki = wki[j * 64 + e];
        cr = fmaf(aqr, bkr, cr); cr = fmaf(aqi, bki, cr);
        ci = fmaf(aqi, bkr, ci); ci = fmaf(-aqr, bki, ci);
    }
    int idx = (d >> 1) * 128 + 2 * e + (d & 1);   // d-pair packed
    g_Cr[idx] = cr;
    g_Ci[idx] = ci;
}

// ---------------- kernel 1: fully fused pipeline (blend->QK->attn->read) ----------------
__global__ __launch_bounds__(256, 2) void k_main(
    const float* __restrict__ zr, const float* __restrict__ zi,
    const float* __restrict__ mem, const float* __restrict__ ptrv,
    const float* __restrict__ ctrl,
    const float* __restrict__ wvr, const float* __restrict__ wvi,
    float* __restrict__ out,
    int o_mem, int o_ptr, int o_zi)
{
    extern __shared__ float sm[];
    float* sCr   = sm;                 // 4096 (packed d-pairs)
    float* sCi   = sCr + 4096;         // 4096
    float* sMr   = sCi + 4096;         // 2 * 16*66 = 2112
    float* sMi   = sMr + 2112;         // 2112
    float* sMn   = sMi + 2112;         // 2112 (negated imag)
    float* sPr   = sMn + 2112;         // 2112
    float* sPi   = sPr + 2112;         // 2112
    float* sAttn = sPi + 2112;         // 2*16*17 = 544
    float* sPtr  = sAttn + 544;        // 32
    float* sNp   = sPtr + 32;          // 32
    float* sCw   = sNp + 32;           // 32
    float* sU    = sCw + 32;           // 16*128 = 2048 (u for all 16 batches)
    float* sZ    = sU + 2048;          // 2*128 (z staging for current pair)

    const int tid = threadIdx.x;
    for (int i = tid; i < 4096; i += 256) { sCr[i] = g_Cr[i]; sCi[i] = g_Ci[i]; }

    const int sg = tid >> 4;   // 0..15 (s row)
    const int ln = tid & 15;   // 0..15 (column group)
    int cnt = 0;

    const int b00 = blockIdx.x * NB;

    // per-thread blend indices (constant across pairs)
    const int pq  = tid >> 7;                // batch within pair for z staging
    const int zd  = tid & 127;
    // prologue prefetch: pair 0
    float4 pf[4];
#pragma unroll
    for (int it = 0; it < 4; ++it) {
        int i4 = tid + it * 256;
        int q  = i4 >> 9;
        int j  = (i4 & 511) * 4;
        pf[it] = *reinterpret_cast<const float4*>(mem + (b00 + q) * 2048 + j);
    }
    sZ[tid] = (zd < 64) ? zr[(b00 + pq) * 64 + zd] : zi[(b00 + pq) * 64 + (zd - 64)];

    for (int bl = 0; bl < NB / 2; ++bl) {
        const int b0 = b00 + bl * 2;
        __syncthreads();   // smem reuse boundary (covers C/sZ prologue on iter 0)

        // gates for both batches (redundant per thread; L1-broadcast loads)
        float push[2], pop[2], stay[2];
#pragma unroll
        for (int q = 0; q < 2; ++q) {
            int b = b0 + q;
            float g0 = 1.f / (1.f + expf(-ctrl[b * 3 + 0]));
            float g1 = 1.f / (1.f + expf(-ctrl[b * 3 + 1]));
            float g2 = 1.f / (1.f + expf(-ctrl[b * 3 + 2]));
            float inv = 1.f / (g0 + g1 + g2 + 1e-6f);
            push[q] = g0 * inv; pop[q] = g1 * inv; stay[q] = g2 * inv;
        }

        if (tid < 32) sPtr[tid] = ptrv[b0 * 16 + tid];   // [q*16+t]

        // mem_new blend for BOTH batches from prefetched regs + staged z
#pragma unroll
        for (int it = 0; it < 4; ++it) {
            int i4 = tid + it * 256;          // 0..1023
            int q  = i4 >> 9;                 // batch within pair
            int j  = (i4 & 511) * 4;          // 0..2044, element offset
            int s_ = j >> 7, d2 = j & 127;
            int b  = b0 + q;
            float4 mv = pf[it];
            float4 zv = *reinterpret_cast<const float4*>(sZ + q * 128 + d2);
            float om = 1.f - push[q], p = push[q];
            float4 nv;
            nv.x = mv.x * om + p * zv.x;
            nv.y = mv.y * om + p * zv.y;
            nv.z = mv.z * om + p * zv.z;
            nv.w = mv.w * om + p * zv.w;
            *reinterpret_cast<float4*>(out + o_mem + b * 2048 + j) = nv;
            int dd = (d2 < 64) ? d2 : (d2 - 64);
            float* dst = ((d2 < 64) ? sMr : sMi) + q * 1056 + s_ * 66 + dd;
            dst[0] = nv.x; dst[1] = nv.y; dst[2] = nv.z; dst[3] = nv.w;
            if (d2 >= 64) {
                float* dn = sMn + q * 1056 + s_ * 66 + dd;
                dn[0] = -nv.x; dn[1] = -nv.y; dn[2] = -nv.z; dn[3] = -nv.w;
            }
        }
        __syncthreads();

        // prefetch NEXT pair while compute phases run (hides DRAM latency)
        if (bl < NB / 2 - 1) {
            const int bn = b0 + 2;
#pragma unroll
            for (int it = 0; it < 4; ++it) {
                int i4 = tid + it * 256;
                int q  = i4 >> 9;
                int j  = (i4 & 511) * 4;
                pf[it] = *reinterpret_cast<const float4*>(mem + (bn + q) * 2048 + j);
            }
            sZ[tid] = (zd < 64) ? zr[(bn + pq) * 64 + zd] : zi[(bn + pq) * 64 + (zd - 64)];
        }

        // new_ptr (roll-mix) + slot count for both batches (warp 0)
        if (tid < 32) {
            int q = tid >> 4, t = tid & 15, b = b0 + q;
            float np = push[q] * sPtr[q * 16 + ((t + 15) & 15)]
                     + pop[q]  * sPtr[q * 16 + ((t + 1) & 15)]
                     + stay[q] * sPtr[q * 16 + t];
            sNp[tid] = np;
            out[o_ptr + b * 16 + t] = np;
            unsigned bal = __ballot_sync(0xFFFFFFFFu, np > 0.1f);
            if (tid == 0) cnt += __popc(bal);
        }

        // ---- P = M * C (complex), packed-over-d f32x2, 2 batches share C loads ----
        unsigned long long apr[2][4] = {{0,0,0,0},{0,0,0,0}};
        unsigned long long api[2][4] = {{0,0,0,0},{0,0,0,0}};
#pragma unroll 4
        for (int d2 = 0; d2 < 32; ++d2) {
            const float* crow  = sCr + d2 * 128 + 2 * ln;
            const float* cirow = sCi + d2 * 128 + 2 * ln;
            unsigned long long c0r = L64(crow);       unsigned long long c0i = L64(cirow);
            unsigned long long c1r = L64(crow + 32);  unsigned long long c1i = L64(cirow + 32);
            unsigned long long c2r = L64(crow + 64);  unsigned long long c2i = L64(cirow + 64);
            unsigned long long c3r = L64(crow + 96);  unsigned long long c3i = L64(cirow + 96);
#pragma unroll
            for (int q = 0; q < 2; ++q) {
                int mo = q * 1056 + sg * 66 + 2 * d2;
                unsigned long long m_r = L64(sMr + mo);
                unsigned long long m_i = L64(sMi + mo);
                unsigned long long m_n = L64(sMn + mo);
                ffma2(apr[q][0], m_r, c0r); ffma2(apr[q][0], m_n, c0i);
                ffma2(api[q][0], m_r, c0i); ffma2(api[q][0], m_i, c0r);
                ffma2(apr[q][1], m_r, c1r); ffma2(apr[q][1], m_n, c1i);
                ffma2(api[q][1], m_r, c1i); ffma2(api[q][1], m_i, c1r);
                ffma2(apr[q][2], m_r, c2r); ffma2(apr[q][2], m_n, c2i);
                ffma2(api[q][2], m_r, c2i); ffma2(api[q][2], m_i, c2r);
                ffma2(apr[q][3], m_r, c3r); ffma2(apr[q][3], m_n, c3i);
                ffma2(api[q][3], m_r, c3i); ffma2(api[q][3], m_i, c3r);
            }
        }
#pragma unroll
        for (int q = 0; q < 2; ++q)
#pragma unroll
            for (int k = 0; k < 4; ++k) {
                sPr[q * 1056 + sg * 66 + ln + 16 * k] = hadd2(apr[q][k]);
                sPi[q * 1056 + sg * 66 + ln + 16 * k] = hadd2(api[q][k]);
            }
        __syncthreads();

        // ---- scores + softmax for both batches ----
#pragma unroll
        for (int q = 0; q < 2; ++q) {
            const float* pr = sPr + q * 1056 + sg * 66;
            const float* pi = sPi + q * 1056 + sg * 66;
            const float* mr = sMr + q * 1056 + ln * 66;
            const float* mi = sMi + q * 1056 + ln * 66;
            unsigned long long acc = 0;
#pragma unroll 8
            for (int d2 = 0; d2 < 32; ++d2) {
                ffma2(acc, L64(pr + 2 * d2), L64(mr + 2 * d2));
                ffma2(acc, L64(pi + 2 * d2), L64(mi + 2 * d2));
            }
            float sc = hadd2(acc) * 0.125f;   // D^-0.5
            float mx = sc;
            mx = fmaxf(mx, __shfl_xor_sync(0xFFFFFFFFu, mx, 8, 16));
            mx = fmaxf(mx, __shfl_xor_sync(0xFFFFFFFFu, mx, 4, 16));
            mx = fmaxf(mx, __shfl_xor_sync(0xFFFFFFFFu, mx, 2, 16));
            mx = fmaxf(mx, __shfl_xor_sync(0xFFFFFFFFu, mx, 1, 16));
            float ex = expf(sc - mx);
            float sme = ex;
            sme += __shfl_xor_sync(0xFFFFFFFFu, sme, 8, 16);
            sme += __shfl_xor_sync(0xFFFFFFFFu, sme, 4, 16);
            sme += __shfl_xor_sync(0xFFFFFFFFu, sme, 2, 16);
            sme += __shfl_xor_sync(0xFFFFFFFFu, sme, 1, 16);
            sAttn[q * 272 + sg * 17 + ln] = ex / sme;
        }
        __syncthreads();

        // cw[t] = sum_s np[s] * attn[s,t] (both batches, warp 0)
        if (tid < 32) {
            int q = tid >> 4, t = tid & 15;
            float a = 0.f;
#pragma unroll
            for (int s2 = 0; s2 < 16; ++s2)
                a = fmaf(sNp[q * 16 + s2], sAttn[q * 272 + s2 * 17 + t], a);
            sCw[tid] = a;
        }
        __syncthreads();

        // u[d] = sum_t cw[t] * M[t,d] -> stage in smem for the fused read tail
        {
            int q = tid >> 7, idx = tid & 127;
            int ri = idx >> 6, d2 = idx & 63;
            const float* Mrow = ((ri == 0) ? sMr : sMi) + q * 1056;
            float a = 0.f;
#pragma unroll
            for (int t2 = 0; t2 < 16; ++t2)
                a = fmaf(sCw[q * 16 + t2], Mrow[t2 * 66 + d2], a);
            sU[(bl * 2 + q) * 128 + ri * 64 + d2] = a;
        }
    }
    __syncthreads();

    // ---- fused read tail: z_read = u * Wv^T (complex) for this CTA's 16 batches ----
    {
        const int blb = tid >> 4;            // local batch 0..15
        const int lnn = tid & 15;            // j group
        const float* ub = sU + blb * 128;
        const int b = b00 + blb;
#pragma unroll
        for (int k = 0; k < 4; ++k) {
            int j = lnn + 16 * k;
            const float4* wrp = reinterpret_cast<const float4*>(wvr + j * 64);
            const float4* wip = reinterpret_cast<const float4*>(wvi + j * 64);
            float accr = 0.f, acci = 0.f;
#pragma unroll
            for (int d4 = 0; d4 < 16; ++d4) {
                float4 wr = __ldg(wrp + d4);
                float4 wi = __ldg(wip + d4);
                float4 ur = *reinterpret_cast<const float4*>(ub + 4 * d4);
                float4 ui = *reinterpret_cast<const float4*>(ub + 64 + 4 * d4);
                accr = fmaf(ur.x, wr.x, accr); accr = fmaf(-ui.x, wi.x, accr);
                accr = fmaf(ur.y, wr.y, accr); accr = fmaf(-ui.y, wi.y, accr);
                accr = fmaf(ur.z, wr.z, accr); accr = fmaf(-ui.z, wi.z, accr);
                accr = fmaf(ur.w, wr.w, accr); accr = fmaf(-ui.w, wi.w, accr);
                acci = fmaf(ui.x, wr.x, acci); acci = fmaf(ur.x, wi.x, acci);
                acci = fmaf(ui.y, wr.y, acci); acci = fmaf(ur.y, wi.y, acci);
                acci = fmaf(ui.z, wr.z, acci); acci = fmaf(ur.z, wi.z, acci);
                acci = fmaf(ui.w, wr.w, acci); acci = fmaf(ur.w, wi.w, acci);
            }
            out[b * 64 + j]        = accr;
            out[o_zi + b * 64 + j] = acci;
        }
    }

    if (tid == 0) atomicAdd(&g_count, cnt);
}

// ---------------- kernel 2: active_slots scalar ----------------
__global__ void k_final(float* __restrict__ out, int o_scal, float invB) {
    out[o_scal] = (float)g_count * invB;
}

// ---------------- launch ----------------
extern "C" void kernel_launch(void* const* d_in, const int* in_sizes, int n_in,
                              void* d_out, int out_size) {
    const float* zr   = (const float*)d_in[0];
    const float* zi   = (const float*)d_in[1];
    const float* mem  = (const float*)d_in[2];
    const float* ptrv = (const float*)d_in[3];
    const float* ctrl = (const float*)d_in[4];
    const float* wqr  = (const float*)d_in[5];
    const float* wqi  = (const float*)d_in[6];
    const float* wkr  = (const float*)d_in[7];
    const float* wki  = (const float*)d_in[8];
    const float* wvr  = (const float*)d_in[9];
    const float* wvi  = (const float*)d_in[10];
    float* out = (float*)d_out;

    const int B = in_sizes[0] / 64;               // 16384
    const int o_zi   = B * 64;
    const int o_mem  = 2 * B * 64;                // after z_read_real|imag
    const int o_ptr  = o_mem + B * 2048;          // after mem_new
    const int o_scal = o_ptr + B * 16;            // active_slots scalar

    // floats: 2*4096 (C) + 5*2112 (tiles) + 544 (attn) + 96 + 2048 (U) + 256 (Z)
    const int smem_bytes = (4096 * 2 + 5 * 2112 + 544 + 96 + 2048 + 256) * (int)sizeof(float);
    cudaFuncSetAttribute(k_main, cudaFuncAttributeMaxDynamicSharedMemorySize, smem_bytes);

    k_prep<<<64, 64>>>(wqr, wqi, wkr, wki);
    k_main<<<B / NB, 256, smem_bytes>>>(zr, zi, mem, ptrv, ctrl, wvr, wvi, out,
                                        o_mem, o_ptr, o_zi);
    k_final<<<1, 1>>>(out, o_scal, 1.f / (float)B);
}

// round 9
// speedup vs baseline: 1.2589x; 1.2589x over previous
#include <cuda_runtime.h>
#include <math.h>

#define D 64
#define S 16
#define NB 16   // batches per CTA in k_main (processed in pairs)

// ---------------- device scratch (static, no runtime alloc) ----------------
// C stored PACKED along d: float pair {C[2*d2][e], C[2*d2+1][e]} at offset d2*128 + 2*e
__device__ float g_Cr[64 * 64];
__device__ float g_Ci[64 * 64];
__device__ float g_U[16384 * 128];   // per-batch u vector (real 64 | imag 64)
__device__ int   g_count;
__device__ unsigned int g_done;

// ---------------- f32x2 packed helpers ----------------
__device__ __forceinline__ void ffma2(unsigned long long& d_,
                                      unsigned long long a_, unsigned long long b_) {
    asm("fma.rn.f32x2 %0, %1, %2, %0;" : "+l"(d_) : "l"(a_), "l"(b_));
}
__device__ __forceinline__ float hadd2(unsigned long long v) {
    float lo, hi;
    asm("mov.b64 {%0, %1}, %2;" : "=f"(lo), "=f"(hi) : "l"(v));
    return lo + hi;
}
__device__ __forceinline__ unsigned long long L64(const float* p) {
    return *reinterpret_cast<const unsigned long long*>(p);
}
// cp.async 16B GMEM->SMEM (no register transit)
__device__ __forceinline__ void cp16(float* s, const float* g) {
    unsigned sa = (unsigned)__cvta_generic_to_shared(s);
    asm volatile("cp.async.cg.shared.global [%0], [%1], 16;" :: "r"(sa), "l"(g));
}
#define CP_COMMIT()  asm volatile("cp.async.commit_group;" ::: "memory")
#define CP_WAIT1()   asm volatile("cp.async.wait_group 1;" ::: "memory")
#define CP_WAIT0()   asm volatile("cp.async.wait_group 0;" ::: "memory")

// ---------------- kernel 0: C = Wq^T * conj(Wk) (packed layout), zero counters ----------------
__global__ __launch_bounds__(256) void k_prep(
    const float* __restrict__ wqr, const float* __restrict__ wqi,
    const float* __restrict__ wkr, const float* __restrict__ wki) {
    __shared__ float sPartR[256];
    __shared__ float sPartI[256];
    const int d  = blockIdx.x;     // 64 blocks
    const int e  = threadIdx.x & 63;
    const int jq = threadIdx.x >> 6;   // 0..3, 16 j's each
    if (d == 0 && threadIdx.x == 0) { g_count = 0; g_done = 0; }
    float cr = 0.f, ci = 0.f;
#pragma unroll
    for (int jj = 0; jj < 16; ++jj) {
        int j = jq * 16 + jj;
        float aqr = wqr[j * 64 + d], aqi = wqi[j * 64 + d];
        float bkr = wkr[j * 64 + e], bki = wki[j * 64 + e];
        cr = fmaf(aqr, bkr, cr); cr = fmaf(aqi, bki, cr);
        ci = fmaf(aqi, bkr, ci); ci = fmaf(-aqr, bki, ci);
    }
    sPartR[threadIdx.x] = cr;
    sPartI[threadIdx.x] = ci;
    __syncthreads();
    if (threadIdx.x < 64) {
        float tr = sPartR[e] + sPartR[64 + e] + sPartR[128 + e] + sPartR[192 + e];
        float ti = sPartI[e] + sPartI[64 + e] + sPartI[128 + e] + sPartI[192 + e];
        int idx = (d >> 1) * 128 + 2 * e + (d & 1);   // d-pair packed
        g_Cr[idx] = tr;
        g_Ci[idx] = ti;
    }
}

// ---------------- kernel 1: main fused per-batch pipeline (2-batch blocked) ----------------
__global__ __launch_bounds__(256, 2) void k_main(
    const float* __restrict__ zr, const float* __restrict__ zi,
    const float* __restrict__ mem, const float* __restrict__ ptrv,
    const float* __restrict__ ctrl, float* __restrict__ out,
    int o_mem, int o_ptr, int o_scal, float invB)
{
    extern __shared__ float sm[];
    float* sCr   = sm;                 // 4096 (packed d-pairs)
    float* sCi   = sCr + 4096;         // 4096
    float* sMr   = sCi + 4096;         // 2 * 16*66 = 2112
    float* sMi   = sMr + 2112;         // 2112
    float* sMn   = sMi + 2112;         // 2112 (negated imag)
    float* sPr   = sMn + 2112;         // 2112
    float* sPi   = sPr + 2112;         // 2112
    float* sAttn = sPi + 2112;         // 2*16*17 = 544
    float* sPtr  = sAttn + 544;        // 32
    float* sNp   = sPtr + 32;          // 32
    float* sCw   = sNp + 32;           // 32
    float* sStage = sCw + 32;          // 2 * 4096 (double-buffered mem staging)

    const int tid = threadIdx.x;
    for (int i = tid; i < 4096; i += 256) { sCr[i] = g_Cr[i]; sCi[i] = g_Ci[i]; }

    const int sg = tid >> 4;   // 0..15 (s row)
    const int ln = tid & 15;   // 0..15 (column group)
    int cnt = 0;

    const int b00 = blockIdx.x * NB;

    // prologue: stage pair 0 via cp.async
#pragma unroll
    for (int it = 0; it < 4; ++it) {
        int i4 = tid + it * 256;
        int q  = i4 >> 9;
        int j  = (i4 & 511) * 4;
        cp16(sStage + i4 * 4, mem + (b00 + q) * 2048 + j);
    }
    CP_COMMIT();

    for (int bl = 0; bl < NB / 2; ++bl) {
        const int b0 = b00 + bl * 2;
        const int buf = bl & 1;

        // issue next pair's staging, then wait for current pair
        if (bl < NB / 2 - 1) {
            const int bn = b0 + 2;
            float* dst = sStage + ((bl + 1) & 1) * 4096;
#pragma unroll
            for (int it = 0; it < 4; ++it) {
                int i4 = tid + it * 256;
                int q  = i4 >> 9;
                int j  = (i4 & 511) * 4;
                cp16(dst + i4 * 4, mem + (bn + q) * 2048 + j);
            }
            CP_COMMIT();
            CP_WAIT1();
        } else {
            CP_WAIT0();
        }
        __syncthreads();   // staged data + smem reuse boundary

        // gates for both batches (redundant per thread; L1-broadcast loads)
        float push[2], pop[2], stay[2];
#pragma unroll
        for (int q = 0; q < 2; ++q) {
            int b = b0 + q;
            float g0 = 1.f / (1.f + __expf(-ctrl[b * 3 + 0]));
            float g1 = 1.f / (1.f + __expf(-ctrl[b * 3 + 1]));
            float g2 = 1.f / (1.f + __expf(-ctrl[b * 3 + 2]));
            float inv = 1.f / (g0 + g1 + g2 + 1e-6f);
            push[q] = g0 * inv; pop[q] = g1 * inv; stay[q] = g2 * inv;
        }

        if (tid < 32) sPtr[tid] = ptrv[b0 * 16 + tid];   // [q*16+t]

        // mem_new blend for BOTH batches from staged smem (no LDG latency)
#pragma unroll
        for (int it = 0; it < 4; ++it) {
            int i4 = tid + it * 256;          // 0..1023
            int q  = i4 >> 9;                 // batch within pair
            int j  = (i4 & 511) * 4;          // 0..2044, element offset
            int s_ = j >> 7, d2 = j & 127;
            int b  = b0 + q;
            float4 mv = *reinterpret_cast<const float4*>(sStage + buf * 4096 + i4 * 4);
            const float* zp = (d2 < 64) ? (zr + b * 64 + d2) : (zi + b * 64 + (d2 - 64));
            float4 zv = *reinterpret_cast<const float4*>(zp);
            float om = 1.f - push[q], p = push[q];
            float4 nv;
            nv.x = mv.x * om + p * zv.x;
            nv.y = mv.y * om + p * zv.y;
            nv.z = mv.z * om + p * zv.z;
            nv.w = mv.w * om + p * zv.w;
            *reinterpret_cast<float4*>(out + o_mem + b * 2048 + j) = nv;
            int dd = (d2 < 64) ? d2 : (d2 - 64);
            float* dst = ((d2 < 64) ? sMr : sMi) + q * 1056 + s_ * 66 + dd;
            dst[0] = nv.x; dst[1] = nv.y; dst[2] = nv.z; dst[3] = nv.w;
            if (d2 >= 64) {
                float* dn = sMn + q * 1056 + s_ * 66 + dd;
                dn[0] = -nv.x; dn[1] = -nv.y; dn[2] = -nv.z; dn[3] = -nv.w;
            }
        }
        __syncthreads();

        // new_ptr (roll-mix) + slot count for both batches (warp 0)
        if (tid < 32) {
            int q = tid >> 4, t = tid & 15, b = b0 + q;
            float np = push[q] * sPtr[q * 16 + ((t + 15) & 15)]
                     + pop[q]  * sPtr[q * 16 + ((t + 1) & 15)]
                     + stay[q] * sPtr[q * 16 + t];
            sNp[tid] = np;
            out[o_ptr + b * 16 + t] = np;
            unsigned bal = __ballot_sync(0xFFFFFFFFu, np > 0.1f);
            if (tid == 0) cnt += __popc(bal);
        }

        // ---- P = M * C (complex), packed-over-d f32x2, 2 batches share C loads ----
        unsigned long long apr[2][4] = {{0,0,0,0},{0,0,0,0}};
        unsigned long long api[2][4] = {{0,0,0,0},{0,0,0,0}};
#pragma unroll 4
        for (int d2 = 0; d2 < 32; ++d2) {
            const float* crow  = sCr + d2 * 128 + 2 * ln;
            const float* cirow = sCi + d2 * 128 + 2 * ln;
            unsigned long long c0r = L64(crow);       unsigned long long c0i = L64(cirow);
            unsigned long long c1r = L64(crow + 32);  unsigned long long c1i = L64(cirow + 32);
            unsigned long long c2r = L64(crow + 64);  unsigned long long c2i = L64(cirow + 64);
            unsigned long long c3r = L64(crow + 96);  unsigned long long c3i = L64(cirow + 96);
#pragma unroll
            for (int q = 0; q < 2; ++q) {
                int mo = q * 1056 + sg * 66 + 2 * d2;
                unsigned long long m_r = L64(sMr + mo);
                unsigned long long m_i = L64(sMi + mo);
                unsigned long long m_n = L64(sMn + mo);
                ffma2(apr[q][0], m_r, c0r); ffma2(apr[q][0], m_n, c0i);
                ffma2(api[q][0], m_r, c0i); ffma2(api[q][0], m_i, c0r);
                ffma2(apr[q][1], m_r, c1r); ffma2(apr[q][1], m_n, c1i);
                ffma2(api[q][1], m_r, c1i); ffma2(api[q][1], m_i, c1r);
                ffma2(apr[q][2], m_r, c2r); ffma2(apr[q][2], m_n, c2i);
                ffma2(api[q][2], m_r, c2i); ffma2(api[q][2], m_i, c2r);
                ffma2(apr[q][3], m_r, c3r); ffma2(apr[q][3], m_n, c3i);
                ffma2(api[q][3], m_r, c3i); ffma2(api[q][3], m_i, c3r);
            }
        }
#pragma unroll
        for (int q = 0; q < 2; ++q)
#pragma unroll
            for (int k = 0; k < 4; ++k) {
                sPr[q * 1056 + sg * 66 + ln + 16 * k] = hadd2(apr[q][k]);
                sPi[q * 1056 + sg * 66 + ln + 16 * k] = hadd2(api[q][k]);
            }
        __syncthreads();

        // ---- scores + softmax for both batches ----
#pragma unroll
        for (int q = 0; q < 2; ++q) {
            const float* pr = sPr + q * 1056 + sg * 66;
            const float* pi = sPi + q * 1056 + sg * 66;
            const float* mr = sMr + q * 1056 + ln * 66;
            const float* mi = sMi + q * 1056 + ln * 66;
            unsigned long long acc = 0;
#pragma unroll 8
            for (int d2 = 0; d2 < 32; ++d2) {
                ffma2(acc, L64(pr + 2 * d2), L64(mr + 2 * d2));
                ffma2(acc, L64(pi + 2 * d2), L64(mi + 2 * d2));
            }
            float sc = hadd2(acc) * 0.125f;   // D^-0.5
            float mx = sc;
            mx = fmaxf(mx, __shfl_xor_sync(0xFFFFFFFFu, mx, 8, 16));
            mx = fmaxf(mx, __shfl_xor_sync(0xFFFFFFFFu, mx, 4, 16));
            mx = fmaxf(mx, __shfl_xor_sync(0xFFFFFFFFu, mx, 2, 16));
            mx = fmaxf(mx, __shfl_xor_sync(0xFFFFFFFFu, mx, 1, 16));
            float ex = __expf(sc - mx);
            float sme = ex;
            sme += __shfl_xor_sync(0xFFFFFFFFu, sme, 8, 16);
            sme += __shfl_xor_sync(0xFFFFFFFFu, sme, 4, 16);
            sme += __shfl_xor_sync(0xFFFFFFFFu, sme, 2, 16);
            sme += __shfl_xor_sync(0xFFFFFFFFu, sme, 1, 16);
            sAttn[q * 272 + sg * 17 + ln] = ex / sme;
        }
        __syncthreads();

        // cw[t] = sum_s np[s] * attn[s,t] (both batches, warp 0)
        if (tid < 32) {
            int q = tid >> 4, t = tid & 15;
            float a = 0.f;
#pragma unroll
            for (int s2 = 0; s2 < 16; ++s2)
                a = fmaf(sNp[q * 16 + s2], sAttn[q * 272 + s2 * 17 + t], a);
            sCw[tid] = a;
        }
        __syncthreads();

        // u[d] = sum_t cw[t] * M[t,d] (real|imag, both batches: 2*128 = 256 threads)
        {
            int q = tid >> 7, idx = tid & 127;
            int ri = idx >> 6, d2 = idx & 63;
            const float* Mrow = ((ri == 0) ? sMr : sMi) + q * 1056;
            float a = 0.f;
#pragma unroll
            for (int t2 = 0; t2 < 16; ++t2)
                a = fmaf(sCw[q * 16 + t2], Mrow[t2 * 66 + d2], a);
            g_U[(b0 + q) * 128 + ri * 64 + d2] = a;
        }
    }

    // slot-count accumulation + last-CTA writes the scalar (replaces k_final)
    if (tid == 0) {
        atomicAdd(&g_count, cnt);
        __threadfence();
        unsigned d = atomicAdd(&g_done, 1u);
        if (d == gridDim.x - 1) {
            __threadfence();
            out[o_scal] = (float)(*(volatile int*)&g_count) * invB;
        }
    }
}

// ---------------- kernel 2: z_read = u * Wv^T (complex, f32x2) ----------------
__global__ __launch_bounds__(256) void k_read(const float* __restrict__ wvr,
                                              const float* __restrict__ wvi,
                                              float* __restrict__ out, int o_zi)
{
    __shared__ float sWr[64 * 66];
    __shared__ float sWi[64 * 66];
    __shared__ float sU[16 * 128];
    __shared__ float sUn[16 * 64];

    const int tid = threadIdx.x;
    for (int i = tid; i < 4096; i += 256) {
        int r = i >> 6, c = i & 63;
        sWr[r * 66 + c] = wvr[i];
        sWi[r * 66 + c] = wvi[i];
    }
    const int b0 = blockIdx.x * 16;
    for (int i = tid; i < 2048; i += 256) {
        float v = g_U[b0 * 128 + i];
        sU[i] = v;
        int loc = i & 127;
        if (loc >= 64) sUn[(i >> 7) * 64 + (loc - 64)] = -v;
    }
    __syncthreads();

    const int bl = tid >> 4;   // local batch 0..15
    const int ln = tid & 15;   // j group
    unsigned long long rr[4] = {0, 0, 0, 0}, ri[4] = {0, 0, 0, 0};
#pragma unroll 4
    for (int d2 = 0; d2 < 32; ++d2) {
        unsigned long long ur = L64(sU + bl * 128 + 2 * d2);
        unsigned long long ui = L64(sU + bl * 128 + 64 + 2 * d2);
        unsigned long long un = L64(sUn + bl * 64 + 2 * d2);
#pragma unroll
        for (int k = 0; k < 4; ++k) {
            int j = ln + 16 * k;
            unsigned long long wr = L64(sWr + j * 66 + 2 * d2);
            unsigned long long wi = L64(sWi + j * 66 + 2 * d2);
            ffma2(rr[k], ur, wr); ffma2(rr[k], un, wi);
            ffma2(ri[k], ui, wr); ffma2(ri[k], ur, wi);
        }
    }
    const int b = b0 + bl;
#pragma unroll
    for (int k = 0; k < 4; ++k) {
        out[b * 64 + ln + 16 * k]        = hadd2(rr[k]);
        out[o_zi + b * 64 + ln + 16 * k] = hadd2(ri[k]);
    }
}

// ---------------- launch ----------------
extern "C" void kernel_launch(void* const* d_in, const int* in_sizes, int n_in,
                              void* d_out, int out_size) {
    const float* zr   = (const float*)d_in[0];
    const float* zi   = (const float*)d_in[1];
    const float* mem  = (const float*)d_in[2];
    const float* ptrv = (const float*)d_in[3];
    const float* ctrl = (const float*)d_in[4];
    const float* wqr  = (const float*)d_in[5];
    const float* wqi  = (const float*)d_in[6];
    const float* wkr  = (const float*)d_in[7];
    const float* wki  = (const float*)d_in[8];
    const float* wvr  = (const float*)d_in[9];
    const float* wvi  = (const float*)d_in[10];
    float* out = (float*)d_out;

    const int B = in_sizes[0] / 64;               // 16384
    const int o_mem  = 2 * B * 64;                // after z_read_real|imag
    const int o_ptr  = o_mem + B * 2048;          // after mem_new
    const int o_scal = o_ptr + B * 16;            // active_slots scalar

    // floats: 2*4096 (C) + 5*2112 (tiles) + 544 (attn) + 96 + 2*4096 (staging)
    const int smem_bytes = (4096 * 2 + 5 * 2112 + 544 + 96 + 8192) * (int)sizeof(float);
    cudaFuncSetAttribute(k_main, cudaFuncAttributeMaxDynamicSharedMemorySize, smem_bytes);

    k_prep<<<64, 256>>>(wqr, wqi, wkr, wki);
    k_main<<<B / NB, 256, smem_bytes>>>(zr, zi, mem, ptrv, ctrl, out,
                                        o_mem, o_ptr, o_scal, 1.f / (float)B);
    k_read<<<B / 16, 256>>>(wvr, wvi, out, B * 64);
}

// round 10
// speedup vs baseline: 1.3399x; 1.0643x over previous
#include <cuda_runtime.h>
#include <math.h>

#define D 64
#define S 16
#define NB 16   // batches per CTA in k_main (processed in quads of 4)

// ---------------- device scratch (static, no runtime alloc) ----------------
// C stored PACKED along d: float pair {C[2*d2][e], C[2*d2+1][e]} at offset d2*128 + 2*e
__device__ float g_Cr[64 * 64];
__device__ float g_Ci[64 * 64];
__device__ float g_U[16384 * 128];   // per-batch u vector (real 64 | imag 64)
__device__ int   g_count;
__device__ unsigned int g_done;

#define SGNMASK 0x8000000080000000ULL

// ---------------- f32x2 packed helpers ----------------
__device__ __forceinline__ void ffma2(unsigned long long& d_,
                                      unsigned long long a_, unsigned long long b_) {
    asm("fma.rn.f32x2 %0, %1, %2, %0;" : "+l"(d_) : "l"(a_), "l"(b_));
}
__device__ __forceinline__ float hadd2(unsigned long long v) {
    float lo, hi;
    asm("mov.b64 {%0, %1}, %2;" : "=f"(lo), "=f"(hi) : "l"(v));
    return lo + hi;
}
__device__ __forceinline__ unsigned long long L64(const float* p) {
    return *reinterpret_cast<const unsigned long long*>(p);
}

// ---------------- kernel 0: C = Wq^T * conj(Wk) (packed layout), zero counters ----------------
__global__ __launch_bounds__(256) void k_prep(
    const float* __restrict__ wqr, const float* __restrict__ wqi,
    const float* __restrict__ wkr, const float* __restrict__ wki) {
    __shared__ float sPartR[256];
    __shared__ float sPartI[256];
    const int d  = blockIdx.x;     // 64 blocks
    const int e  = threadIdx.x & 63;
    const int jq = threadIdx.x >> 6;   // 0..3, 16 j's each
    if (d == 0 && threadIdx.x == 0) { g_count = 0; g_done = 0; }
    float cr = 0.f, ci = 0.f;
#pragma unroll
    for (int jj = 0; jj < 16; ++jj) {
        int j = jq * 16 + jj;
        float aqr = wqr[j * 64 + d], aqi = wqi[j * 64 + d];
        float bkr = wkr[j * 64 + e], bki = wki[j * 64 + e];
        cr = fmaf(aqr, bkr, cr); cr = fmaf(aqi, bki, cr);
        ci = fmaf(aqi, bkr, ci); ci = fmaf(-aqr, bki, ci);
    }
    sPartR[threadIdx.x] = cr;
    sPartI[threadIdx.x] = ci;
    __syncthreads();
    if (threadIdx.x < 64) {
        float tr = sPartR[e] + sPartR[64 + e] + sPartR[128 + e] + sPartR[192 + e];
        float ti = sPartI[e] + sPartI[64 + e] + sPartI[128 + e] + sPartI[192 + e];
        int idx = (d >> 1) * 128 + 2 * e + (d & 1);   // d-pair packed
        g_Cr[idx] = tr;
        g_Ci[idx] = ti;
    }
}

// ---------------- kernel 1: main fused pipeline (4-batch quads) ----------------
__global__ __launch_bounds__(256, 2) void k_main(
    const float* __restrict__ zr, const float* __restrict__ zi,
    const float* __restrict__ mem, const float* __restrict__ ptrv,
    const float* __restrict__ ctrl, float* __restrict__ out,
    int o_mem, int o_ptr, int o_scal, float invB)
{
    extern __shared__ float sm[];
    float* sCr   = sm;                 // 4096 (packed d-pairs)
    float* sCi   = sCr + 4096;         // 4096
    float* sMr   = sCi + 4096;         // 4 * 16*66 = 4224
    float* sMi   = sMr + 4224;         // 4224
    float* sPr   = sMi + 4224;         // 4224
    float* sPi   = sPr + 4224;         // 4224
    float* sAttn = sPi + 4224;         // 4*16*17 = 1088
    float* sPtr  = sAttn + 1088;       // 64
    float* sNp   = sPtr + 64;          // 64
    float* sCw   = sNp + 64;           // 64
    float* sCnt  = sCw + 64;           // 8

    const int tid = threadIdx.x;
    for (int i = tid; i < 4096; i += 256) { sCr[i] = g_Cr[i]; sCi[i] = g_Ci[i]; }

    const int sg = tid >> 4;   // 0..15 (s row)
    const int ln = tid & 15;   // 0..15 (column group)
    int cnt = 0;

    const int b00 = blockIdx.x * NB;

    for (int bl = 0; bl < NB / 4; ++bl) {
        const int b0 = b00 + bl * 4;
        __syncthreads();   // smem reuse boundary (covers C load on iter 0)

        // gates for all 4 batches (redundant per thread; L1-broadcast loads)
        float push[4], pop[4], stay[4];
#pragma unroll
        for (int q = 0; q < 4; ++q) {
            int b = b0 + q;
            float g0 = 1.f / (1.f + __expf(-ctrl[b * 3 + 0]));
            float g1 = 1.f / (1.f + __expf(-ctrl[b * 3 + 1]));
            float g2 = 1.f / (1.f + __expf(-ctrl[b * 3 + 2]));
            float inv = 1.f / (g0 + g1 + g2 + 1e-6f);
            push[q] = g0 * inv; pop[q] = g1 * inv; stay[q] = g2 * inv;
        }

        if (tid < 64) sPtr[tid] = ptrv[b0 * 16 + tid];   // [q*16+t]

        // mem_new blend for 4 batches, float4 vectorized (2048 float4 total)
#pragma unroll
        for (int it = 0; it < 8; ++it) {
            int i4 = tid + it * 256;          // 0..2047
            int q  = i4 >> 9;                 // batch within quad
            int j  = (i4 & 511) * 4;          // 0..2044, element offset
            int s_ = j >> 7, d2 = j & 127;
            int b  = b0 + q;
            float4 mv = *reinterpret_cast<const float4*>(mem + b * 2048 + j);
            const float* zp = (d2 < 64) ? (zr + b * 64 + d2) : (zi + b * 64 + (d2 - 64));
            float4 zv = *reinterpret_cast<const float4*>(zp);
            float om = 1.f - push[q], p = push[q];
            float4 nv;
            nv.x = mv.x * om + p * zv.x;
            nv.y = mv.y * om + p * zv.y;
            nv.z = mv.z * om + p * zv.z;
            nv.w = mv.w * om + p * zv.w;
            *reinterpret_cast<float4*>(out + o_mem + b * 2048 + j) = nv;
            int dd = (d2 < 64) ? d2 : (d2 - 64);
            float* dst = ((d2 < 64) ? sMr : sMi) + q * 1056 + s_ * 66 + dd;
            dst[0] = nv.x; dst[1] = nv.y; dst[2] = nv.z; dst[3] = nv.w;
        }
        __syncthreads();

        // new_ptr (roll-mix) + slot count, 4 batches across warps 0-1
        if (tid < 64) {
            int q = tid >> 4, t = tid & 15, b = b0 + q;
            float np = push[q] * sPtr[q * 16 + ((t + 15) & 15)]
                     + pop[q]  * sPtr[q * 16 + ((t + 1) & 15)]
                     + stay[q] * sPtr[q * 16 + t];
            sNp[tid] = np;
            out[o_ptr + b * 16 + t] = np;
            unsigned bal = __ballot_sync(0xFFFFFFFFu, np > 0.1f);
            if ((tid & 31) == 0) sCnt[tid >> 5] = (float)__popc(bal);
        }

        // ---- P = M * C (complex), packed-over-d f32x2, 4 batches share C loads ----
        unsigned long long apr[4][4] = {{0,0,0,0},{0,0,0,0},{0,0,0,0},{0,0,0,0}};
        unsigned long long api[4][4] = {{0,0,0,0},{0,0,0,0},{0,0,0,0},{0,0,0,0}};
#pragma unroll 4
        for (int d2 = 0; d2 < 32; ++d2) {
            const float* crow  = sCr + d2 * 128 + 2 * ln;
            const float* cirow = sCi + d2 * 128 + 2 * ln;
            unsigned long long c0r = L64(crow);       unsigned long long c0i = L64(cirow);
            unsigned long long c1r = L64(crow + 32);  unsigned long long c1i = L64(cirow + 32);
            unsigned long long c2r = L64(crow + 64);  unsigned long long c2i = L64(cirow + 64);
            unsigned long long c3r = L64(crow + 96);  unsigned long long c3i = L64(cirow + 96);
#pragma unroll
            for (int q = 0; q < 4; ++q) {
                int mo = q * 1056 + sg * 66 + 2 * d2;
                unsigned long long m_r = L64(sMr + mo);
                unsigned long long m_i = L64(sMi + mo);
                unsigned long long m_n = m_i ^ SGNMASK;   // -imag via ALU-pipe XOR
                ffma2(apr[q][0], m_r, c0r); ffma2(apr[q][0], m_n, c0i);
                ffma2(api[q][0], m_r, c0i); ffma2(api[q][0], m_i, c0r);
                ffma2(apr[q][1], m_r, c1r); ffma2(apr[q][1], m_n, c1i);
                ffma2(api[q][1], m_r, c1i); ffma2(api[q][1], m_i, c1r);
                ffma2(apr[q][2], m_r, c2r); ffma2(apr[q][2], m_n, c2i);
                ffma2(api[q][2], m_r, c2i); ffma2(api[q][2], m_i, c2r);
                ffma2(apr[q][3], m_r, c3r); ffma2(apr[q][3], m_n, c3i);
                ffma2(api[q][3], m_r, c3i); ffma2(api[q][3], m_i, c3r);
            }
        }
#pragma unroll
        for (int q = 0; q < 4; ++q)
#pragma unroll
            for (int k = 0; k < 4; ++k) {
                sPr[q * 1056 + sg * 66 + ln + 16 * k] = hadd2(apr[q][k]);
                sPi[q * 1056 + sg * 66 + ln + 16 * k] = hadd2(api[q][k]);
            }
        __syncthreads();

        // slot-count accumulation (sCnt written pre-GEMM, barrier passed)
        if (tid == 0) cnt += (int)sCnt[0] + (int)sCnt[1];

        // ---- scores + softmax for 4 batches ----
#pragma unroll
        for (int q = 0; q < 4; ++q) {
            const float* pr = sPr + q * 1056 + sg * 66;
            const float* pi = sPi + q * 1056 + sg * 66;
            const float* mr = sMr + q * 1056 + ln * 66;
            const float* mi = sMi + q * 1056 + ln * 66;
            unsigned long long acc = 0;
#pragma unroll 8
            for (int d2 = 0; d2 < 32; ++d2) {
                ffma2(acc, L64(pr + 2 * d2), L64(mr + 2 * d2));
                ffma2(acc, L64(pi + 2 * d2), L64(mi + 2 * d2));
            }
            float sc = hadd2(acc) * 0.125f;   // D^-0.5
            float mx = sc;
            mx = fmaxf(mx, __shfl_xor_sync(0xFFFFFFFFu, mx, 8, 16));
            mx = fmaxf(mx, __shfl_xor_sync(0xFFFFFFFFu, mx, 4, 16));
            mx = fmaxf(mx, __shfl_xor_sync(0xFFFFFFFFu, mx, 2, 16));
            mx = fmaxf(mx, __shfl_xor_sync(0xFFFFFFFFu, mx, 1, 16));
            float ex = __expf(sc - mx);
            float sme = ex;
            sme += __shfl_xor_sync(0xFFFFFFFFu, sme, 8, 16);
            sme += __shfl_xor_sync(0xFFFFFFFFu, sme, 4, 16);
            sme += __shfl_xor_sync(0xFFFFFFFFu, sme, 2, 16);
            sme += __shfl_xor_sync(0xFFFFFFFFu, sme, 1, 16);
            sAttn[q * 272 + sg * 17 + ln] = ex / sme;
        }
        __syncthreads();

        // cw[t] = sum_s np[s] * attn[s,t] (4 batches, warps 0-1)
        if (tid < 64) {
            int q = tid >> 4, t = tid & 15;
            float a = 0.f;
#pragma unroll
            for (int s2 = 0; s2 < 16; ++s2)
                a = fmaf(sNp[q * 16 + s2], sAttn[q * 272 + s2 * 17 + t], a);
            sCw[tid] = a;
        }
        __syncthreads();

        // u[d] = sum_t cw[t] * M[t,d] (real|imag, 4 batches: 512 outputs, 2 passes)
#pragma unroll
        for (int h = 0; h < 2; ++h) {
            int idx = tid + h * 256;          // 0..511
            int q = idx >> 7;
            int l = idx & 127;
            int ri = l >> 6, d2 = l & 63;
            const float* Mrow = ((ri == 0) ? sMr : sMi) + q * 1056;
            float a = 0.f;
#pragma unroll
            for (int t2 = 0; t2 < 16; ++t2)
                a = fmaf(sCw[q * 16 + t2], Mrow[t2 * 66 + d2], a);
            g_U[(b0 + q) * 128 + ri * 64 + d2] = a;
        }
    }

    // slot-count + last-CTA scalar write (replaces k_final)
    if (tid == 0) {
        atomicAdd(&g_count, cnt);
        __threadfence();
        unsigned d = atomicAdd(&g_done, 1u);
        if (d == gridDim.x - 1) {
            __threadfence();
            out[o_scal] = (float)(*(volatile int*)&g_count) * invB;
        }
    }
}

// ---------------- kernel 2: z_read = u * Wv^T (complex, f32x2) ----------------
__global__ __launch_bounds__(256) void k_read(const float* __restrict__ wvr,
                                              const float* __restrict__ wvi,
                                              float* __restrict__ out, int o_zi)
{
    __shared__ float sWr[64 * 66];
    __shared__ float sWi[64 * 66];
    __shared__ float sU[16 * 128];
    __shared__ float sUn[16 * 64];

    const int tid = threadIdx.x;
    for (int i = tid; i < 4096; i += 256) {
        int r = i >> 6, c = i & 63;
        sWr[r * 66 + c] = wvr[i];
        sWi[r * 66 + c] = wvi[i];
    }
    const int b0 = blockIdx.x * 16;
    for (int i = tid; i < 2048; i += 256) {
        float v = g_U[b0 * 128 + i];
        sU[i] = v;
        int loc = i & 127;
        if (loc >= 64) sUn[(i >> 7) * 64 + (loc - 64)] = -v;
    }
    __syncthreads();

    const int bl = tid >> 4;   // local batch 0..15
    const int ln = tid & 15;   // j group
    unsigned long long rr[4] = {0, 0, 0, 0}, ri[4] = {0, 0, 0, 0};
#pragma unroll 4
    for (int d2 = 0; d2 < 32; ++d2) {
        unsigned long long ur = L64(sU + bl * 128 + 2 * d2);
        unsigned long long ui = L64(sU + bl * 128 + 64 + 2 * d2);
        unsigned long long un = L64(sUn + bl * 64 + 2 * d2);
#pragma unroll
        for (int k = 0; k < 4; ++k) {
            int j = ln + 16 * k;
            unsigned long long wr = L64(sWr + j * 66 + 2 * d2);
            unsigned long long wi = L64(sWi + j * 66 + 2 * d2);
            ffma2(rr[k], ur, wr); ffma2(rr[k], un, wi);
            ffma2(ri[k], ui, wr); ffma2(ri[k], ur, wi);
        }
    }
    const int b = b0 + bl;
#pragma unroll
    for (int k = 0; k < 4; ++k) {
        out[b * 64 + ln + 16 * k]        = hadd2(rr[k]);
        out[o_zi + b * 64 + ln + 16 * k] = hadd2(ri[k]);
    }
}

// ---------------- launch ----------------
extern "C" void kernel_launch(void* const* d_in, const int* in_sizes, int n_in,
                              void* d_out, int out_size) {
    const float* zr   = (const float*)d_in[0];
    const float* zi   = (const float*)d_in[1];
    const float* mem  = (const float*)d_in[2];
    const float* ptrv = (const float*)d_in[3];
    const float* ctrl = (const float*)d_in[4];
    const float* wqr  = (const float*)d_in[5];
    const float* wqi  = (const float*)d_in[6];
    const float* wkr  = (const float*)d_in[7];
    const float* wki  = (const float*)d_in[8];
    const float* wvr  = (const float*)d_in[9];
    const float* wvi  = (const float*)d_in[10];
    float* out = (float*)d_out;

    const int B = in_sizes[0] / 64;               // 16384
    const int o_mem  = 2 * B * 64;                // after z_read_real|imag
    const int o_ptr  = o_mem + B * 2048;          // after mem_new
    const int o_scal = o_ptr + B * 16;            // active_slots scalar

    // floats: 2*4096 (C) + 4*4224 (M/P tiles) + 1088 (attn) + 200 misc
    const int smem_bytes = (4096 * 2 + 4 * 4224 + 1088 + 200) * (int)sizeof(float);
    cudaFuncSetAttribute(k_main, cudaFuncAttributeMaxDynamicSharedMemorySize, smem_bytes);

    k_prep<<<64, 256>>>(wqr, wqi, wkr, wki);
    k_main<<<B / NB, 256, smem_bytes>>>(zr, zi, mem, ptrv, ctrl, out,
                                        o_mem, o_ptr, o_scal, 1.f / (float)B);
    k_read<<<B / 16, 256>>>(wvr, wvi, out, B * 64);
}